// round 2
// baseline (speedup 1.0000x reference)
#include <cuda_runtime.h>

// Att_mask: fused low-rank tanh attention + Laplacian reconstruction.
// One warp processes one batch b: lane = r (0..31).
//   Q/K/V = tanh(A* @ x[b])  -> lane r holds row r (16 agents) as 8 f32x2 pairs
//   scores[r,s] = (Q[r,:].K[s,:]) * rsqrt(nn); e = exp(scores); (no max-sub: |score|<=16)
//   o[r,:] += e_s * V[s,:];  c[:] = sum_r (Ao[r]/esum_r) * o[r,:]  (warp butterfly)
//   R2 = tanh(c)^2 ; out[b,j] = (j==i)? sum(R2) : -R2[j],  i = b%16
// All heavy FMA work uses packed fma.rn.f32x2 (FFMA2) to halve FMA-pipe pressure.

typedef unsigned long long ull;

#define WARPS_PER_BLOCK 8
#define ITERS 8
#define NBLOCKS 1024            // 1024 * 8 warps * 8 iters = 65536 batches

__device__ __forceinline__ ull pack2(float lo, float hi) {
    ull r; asm("mov.b64 %0, {%1, %2};" : "=l"(r) : "f"(lo), "f"(hi)); return r;
}
__device__ __forceinline__ void unpack2(ull v, float& lo, float& hi) {
    asm("mov.b64 {%0, %1}, %2;" : "=f"(lo), "=f"(hi) : "l"(v));
}
__device__ __forceinline__ void fma2(ull& d, ull a, ull b) {
    asm("fma.rn.f32x2 %0, %1, %2, %0;" : "+l"(d) : "l"(a), "l"(b));
}
__device__ __forceinline__ ull mul2(ull a, ull b) {
    ull r; asm("mul.rn.f32x2 %0, %1, %2;" : "=l"(r) : "l"(a), "l"(b)); return r;
}
__device__ __forceinline__ ull add2(ull a, ull b) {
    ull r; asm("add.rn.f32x2 %0, %1, %2;" : "=l"(r) : "l"(a), "l"(b)); return r;
}
// Accurate-enough tanh: 1 - 2/(exp(2x)+1). 2 MUFU ops, rel err ~1e-6.
__device__ __forceinline__ float fast_tanh(float x) {
    float e = __expf(2.0f * x);
    return 1.0f - __fdividef(2.0f, e + 1.0f);
}

// Shared layout (floats):
//   wT   [3][64][32]  : 6144   (A* transposed to [d][r] -> conflict-free LDS per lane=r)
//   aoS  [32]         : 32
//   per-warp: xs[64*16]=1024, ks[32*20]=640, vs[32*20]=640  (stride-20 rows: STS.128 phase-conflict-free)
#define SMEM_FLOATS (6144 + 32 + WARPS_PER_BLOCK * (1024 + 640 + 640))
#define SMEM_BYTES  (SMEM_FLOATS * 4)

__global__ void __launch_bounds__(256) att_mask_kernel(
    const float* __restrict__ x, const float* __restrict__ L,
    const float* __restrict__ Aq, const float* __restrict__ Ak,
    const float* __restrict__ Av, const float* __restrict__ Ao,
    float* __restrict__ out)
{
    extern __shared__ float sm[];
    const int tid  = threadIdx.x;
    const int warp = tid >> 5;
    const int lane = tid & 31;

    float* wT  = sm;                 // [3][64][32]
    float* aoS = sm + 6144;
    float* wb  = sm + 6144 + 32 + warp * (1024 + 640 + 640);
    float* xs  = wb;                 // [64][16]
    float* ks  = wb + 1024;          // [32][20]
    float* vs  = wb + 1024 + 640;    // [32][20]

    // Stage weights, transposed to [d][r]
    for (int idx = tid; idx < 2048; idx += 256) {
        int r = idx >> 6, d = idx & 63;
        wT[d * 32 + r]        = Aq[idx];
        wT[2048 + d * 32 + r] = Ak[idx];
        wT[4096 + d * 32 + r] = Av[idx];
    }
    if (tid < 32) aoS[tid] = Ao[tid];
    __syncthreads();

    const int gw = blockIdx.x * WARPS_PER_BLOCK + warp;   // 0..8191
    const int r  = lane;
    const float* wq = wT + r;
    const float* wk = wT + 2048 + r;
    const float* wv = wT + 4096 + r;

    for (int it = 0; it < ITERS; ++it) {
        const int b = gw + it * (NBLOCKS * WARPS_PER_BLOCK);

        // ---- stage x[b] (1024 floats, coalesced) ----
        const float4* xg  = (const float4*)(x + (size_t)b * 1024);
        float4*       xs4 = (float4*)xs;
        #pragma unroll
        for (int i = 0; i < 8; ++i) xs4[i * 32 + lane] = xg[i * 32 + lane];

        // ---- numNeighbors from L[b,0,:] ----
        float lv = (lane < 16) ? __ldg(L + (size_t)b * 256 + lane) : 0.0f;
        unsigned mb = __ballot_sync(0xffffffffu, lv >= 1.0f);
        float nn   = (float)(__popc(mb) + 1);
        float scl2 = rsqrtf(nn) * 1.4426950408889634f;   // fold log2(e) for exp2
        __syncwarp();

        // ---- QKV projection: single pass over d, packed pairs over n ----
        ull aq[8], ak[8], av[8];
        #pragma unroll
        for (int p = 0; p < 8; ++p) { aq[p] = 0ull; ak[p] = 0ull; av[p] = 0ull; }

        #pragma unroll 8
        for (int d = 0; d < 64; ++d) {
            float wqv = wq[d * 32], wkv = wk[d * 32], wvv = wv[d * 32];
            ull w2q = pack2(wqv, wqv);
            ull w2k = pack2(wkv, wkv);
            ull w2v = pack2(wvv, wvv);
            const ulonglong2* xp = (const ulonglong2*)(xs + d * 16);
            #pragma unroll
            for (int i = 0; i < 4; ++i) {
                ulonglong2 xv = xp[i];           // 4 floats = 2 pairs (broadcast LDS.128)
                fma2(aq[2 * i], w2q, xv.x);  fma2(aq[2 * i + 1], w2q, xv.y);
                fma2(ak[2 * i], w2k, xv.x);  fma2(ak[2 * i + 1], w2k, xv.y);
                fma2(av[2 * i], w2v, xv.x);  fma2(av[2 * i + 1], w2v, xv.y);
            }
        }

        // ---- tanh; keep Q in regs, K/V to shared ----
        ull q2[8];
        #pragma unroll
        for (int p = 0; p < 8; ++p) {
            float a0, a1; unpack2(aq[p], a0, a1);
            q2[p] = pack2(fast_tanh(a0), fast_tanh(a1));
        }
        {
            float4* kp4 = (float4*)(ks + r * 20);
            float4* vp4 = (float4*)(vs + r * 20);
            #pragma unroll
            for (int p = 0; p < 4; ++p) {
                float a0, a1, a2, a3;
                unpack2(ak[2 * p], a0, a1); unpack2(ak[2 * p + 1], a2, a3);
                kp4[p] = make_float4(fast_tanh(a0), fast_tanh(a1), fast_tanh(a2), fast_tanh(a3));
                unpack2(av[2 * p], a0, a1); unpack2(av[2 * p + 1], a2, a3);
                vp4[p] = make_float4(fast_tanh(a0), fast_tanh(a1), fast_tanh(a2), fast_tanh(a3));
            }
        }
        __syncwarp();

        // ---- scores row r, exp (no max-subtraction needed: |score| <= 16) ----
        float e[32];
        float esum = 0.0f;
        #pragma unroll
        for (int s = 0; s < 32; ++s) {
            const ulonglong2* kp = (const ulonglong2*)(ks + s * 20);
            ull acc = 0ull;
            #pragma unroll
            for (int i = 0; i < 4; ++i) {
                ulonglong2 kv = kp[i];
                fma2(acc, q2[2 * i], kv.x);
                fma2(acc, q2[2 * i + 1], kv.y);
            }
            float lo, hi; unpack2(acc, lo, hi);
            float ev = exp2f((lo + hi) * scl2);
            e[s] = ev; esum += ev;
        }
        float inv = __fdividef(1.0f, esum);

        // ---- o[r,:] = sum_s e_s * V[s,:] (unnormalized) ----
        ull o2[8];
        #pragma unroll
        for (int p = 0; p < 8; ++p) o2[p] = 0ull;
        #pragma unroll
        for (int s = 0; s < 32; ++s) {
            ull e2 = pack2(e[s], e[s]);
            const ulonglong2* vp = (const ulonglong2*)(vs + s * 20);
            #pragma unroll
            for (int i = 0; i < 4; ++i) {
                ulonglong2 vv = vp[i];
                fma2(o2[2 * i], e2, vv.x);
                fma2(o2[2 * i + 1], e2, vv.y);
            }
        }

        // ---- fold Ao[r]/esum_r, butterfly-reduce across lanes ----
        float aw = aoS[r] * inv;
        ull aw2 = pack2(aw, aw);
        #pragma unroll
        for (int p = 0; p < 8; ++p) o2[p] = mul2(o2[p], aw2);
        #pragma unroll
        for (int off = 16; off > 0; off >>= 1) {
            #pragma unroll
            for (int p = 0; p < 8; ++p) {
                ull other = __shfl_xor_sync(0xffffffffu, o2[p], off);
                o2[p] = add2(o2[p], other);
            }
        }

        // ---- final tanh^2 + Laplacian row, lane 0 writes 16 floats ----
        float r2[16]; float rowsum = 0.0f;
        #pragma unroll
        for (int p = 0; p < 8; ++p) {
            float a0, a1; unpack2(o2[p], a0, a1);
            float t0 = fast_tanh(a0), t1 = fast_tanh(a1);
            r2[2 * p] = t0 * t0; r2[2 * p + 1] = t1 * t1;
            rowsum += r2[2 * p] + r2[2 * p + 1];
        }
        if (lane == 0) {
            int i = b & 15;
            float4* og = (float4*)(out + (size_t)b * 16);
            #pragma unroll
            for (int q = 0; q < 4; ++q) {
                float v0 = (4 * q + 0 == i) ? rowsum : -r2[4 * q + 0];
                float v1 = (4 * q + 1 == i) ? rowsum : -r2[4 * q + 1];
                float v2 = (4 * q + 2 == i) ? rowsum : -r2[4 * q + 2];
                float v3 = (4 * q + 3 == i) ? rowsum : -r2[4 * q + 3];
                og[q] = make_float4(v0, v1, v2, v3);
            }
        }
        __syncwarp();
    }
}

extern "C" void kernel_launch(void* const* d_in, const int* in_sizes, int n_in,
                              void* d_out, int out_size) {
    const float* x  = (const float*)d_in[0];
    const float* L  = (const float*)d_in[1];
    const float* Aq = (const float*)d_in[2];
    const float* Ak = (const float*)d_in[3];
    const float* Av = (const float*)d_in[4];
    const float* Ao = (const float*)d_in[5];
    float* out = (float*)d_out;

    cudaFuncSetAttribute(att_mask_kernel,
                         cudaFuncAttributeMaxDynamicSharedMemorySize, SMEM_BYTES);
    att_mask_kernel<<<NBLOCKS, 256, SMEM_BYTES>>>(x, L, Aq, Ak, Av, Ao, out);
}

// round 3
// speedup vs baseline: 1.1319x; 1.1319x over previous
#include <cuda_runtime.h>

// Att_mask: fused low-rank tanh attention + Laplacian reconstruction.
// One warp per batch b; lane = r (0..31). Packed f32x2 (FFMA2) everywhere.
// R3: quad-packed weight loads (LDS.128), fused scores+o pass,
//     split-vector butterfly reduction, finer grid.

typedef unsigned long long ull;

#define WARPS_PER_BLOCK 8
#define ITERS 4
#define NBLOCKS 2048            // 2048 * 8 warps * 4 iters = 65536 batches

__device__ __forceinline__ ull pack2(float lo, float hi) {
    ull r; asm("mov.b64 %0, {%1, %2};" : "=l"(r) : "f"(lo), "f"(hi)); return r;
}
__device__ __forceinline__ void unpack2(ull v, float& lo, float& hi) {
    asm("mov.b64 {%0, %1}, %2;" : "=f"(lo), "=f"(hi) : "l"(v));
}
__device__ __forceinline__ void fma2(ull& d, ull a, ull b) {
    asm("fma.rn.f32x2 %0, %1, %2, %0;" : "+l"(d) : "l"(a), "l"(b));
}
__device__ __forceinline__ ull add2(ull a, ull b) {
    ull r; asm("add.rn.f32x2 %0, %1, %2;" : "=l"(r) : "l"(a), "l"(b)); return r;
}
// tanh via 1 - 2/(exp(2x)+1): 2 MUFU, rel err ~1e-6.
__device__ __forceinline__ float fast_tanh(float x) {
    float e = __expf(2.0f * x);
    return 1.0f - __fdividef(2.0f, e + 1.0f);
}

// Shared layout (floats):
//   wT   [3][16 dq][32 r][4 j] : 6144  (quad-packed: one LDS.128 per matrix per 4 d)
//   aoS  [32]
//   per-warp: xs[64*16]=1024, ks[32*20]=640, vs[32*20]=640
#define SMEM_FLOATS (6144 + 32 + WARPS_PER_BLOCK * (1024 + 640 + 640))
#define SMEM_BYTES  (SMEM_FLOATS * 4)

__global__ void __launch_bounds__(256) att_mask_kernel(
    const float* __restrict__ x, const float* __restrict__ L,
    const float* __restrict__ Aq, const float* __restrict__ Ak,
    const float* __restrict__ Av, const float* __restrict__ Ao,
    float* __restrict__ out)
{
    extern __shared__ float sm[];
    const int tid  = threadIdx.x;
    const int warp = tid >> 5;
    const int lane = tid & 31;

    float* wT  = sm;                 // quad-packed weights
    float* aoS = sm + 6144;
    float* wb  = sm + 6144 + 32 + warp * (1024 + 640 + 640);
    float* xs  = wb;                 // [64][16]
    float* ks  = wb + 1024;          // [32][20]
    float* vs  = wb + 1024 + 640;    // [32][20]

    // Stage weights quad-packed: wT[mat*2048 + (d>>2)*128 + r*4 + (d&3)] = A[r][d]
    for (int idx = tid; idx < 2048; idx += 256) {
        int r = idx >> 6, d = idx & 63;
        int off = ((d >> 2) << 7) + (r << 2) + (d & 3);
        wT[off]        = Aq[idx];
        wT[2048 + off] = Ak[idx];
        wT[4096 + off] = Av[idx];
    }
    if (tid < 32) aoS[tid] = Ao[tid];
    __syncthreads();

    const int gw = blockIdx.x * WARPS_PER_BLOCK + warp;
    const int r  = lane;
    const float* wqp = wT + (r << 2);
    const float* wkp = wT + 2048 + (r << 2);
    const float* wvp = wT + 4096 + (r << 2);

    for (int it = 0; it < ITERS; ++it) {
        const int b = gw + it * (NBLOCKS * WARPS_PER_BLOCK);

        // ---- stage x[b] (1024 floats, coalesced) ----
        const float4* xg  = (const float4*)(x + (size_t)b * 1024);
        float4*       xs4 = (float4*)xs;
        #pragma unroll
        for (int i = 0; i < 8; ++i) xs4[i * 32 + lane] = xg[i * 32 + lane];

        // ---- numNeighbors from L[b,0,:] ----
        float lv = (lane < 16) ? __ldg(L + (size_t)b * 256 + lane) : 0.0f;
        unsigned mb = __ballot_sync(0xffffffffu, lv >= 1.0f);
        float scl2 = rsqrtf((float)(__popc(mb) + 1)) * 1.4426950408889634f;
        __syncwarp();

        // ---- QKV projection over d in quads ----
        ull aq[8], ak[8], av[8];
        #pragma unroll
        for (int p = 0; p < 8; ++p) { aq[p] = 0ull; ak[p] = 0ull; av[p] = 0ull; }

        #pragma unroll 4
        for (int dq = 0; dq < 16; ++dq) {
            float4 wq4 = *(const float4*)(wqp + (dq << 7));
            float4 wk4 = *(const float4*)(wkp + (dq << 7));
            float4 wv4 = *(const float4*)(wvp + (dq << 7));
            const ulonglong2* xp = (const ulonglong2*)(xs + (dq << 6));
            #pragma unroll
            for (int j = 0; j < 4; ++j) {
                float wqv = (j == 0) ? wq4.x : (j == 1) ? wq4.y : (j == 2) ? wq4.z : wq4.w;
                float wkv = (j == 0) ? wk4.x : (j == 1) ? wk4.y : (j == 2) ? wk4.z : wk4.w;
                float wvv = (j == 0) ? wv4.x : (j == 1) ? wv4.y : (j == 2) ? wv4.z : wv4.w;
                ull w2q = pack2(wqv, wqv);
                ull w2k = pack2(wkv, wkv);
                ull w2v = pack2(wvv, wvv);
                ulonglong2 xv0 = xp[2 * j];
                ulonglong2 xv1 = xp[2 * j + 1];
                fma2(aq[0], w2q, xv0.x); fma2(aq[1], w2q, xv0.y);
                fma2(aq[2], w2q, xv1.x); fma2(aq[3], w2q, xv1.y);
                fma2(ak[0], w2k, xv0.x); fma2(ak[1], w2k, xv0.y);
                fma2(ak[2], w2k, xv1.x); fma2(ak[3], w2k, xv1.y);
                fma2(av[0], w2v, xv0.x); fma2(av[1], w2v, xv0.y);
                fma2(av[2], w2v, xv1.x); fma2(av[3], w2v, xv1.y);
                // second half of n (pairs 4..7) from same xv? No: xv covers 8 floats.
                // 16 n = 4 ulonglong2; xp[2j],xp[2j+1] cover only 8 floats. Need xp for full row:
            }
        }
        // NOTE: layout check — xs row d has 16 floats = 4 ulonglong2; the loop
        // above must consume all 4. Corrected below by re-running remaining pairs.
        // (The loop above is restructured here to cover all 4 pairs per d.)
        // -- To keep a single clean pass, redo projection properly: --
        #pragma unroll
        for (int p = 0; p < 8; ++p) { aq[p] = 0ull; ak[p] = 0ull; av[p] = 0ull; }
        #pragma unroll 4
        for (int dq = 0; dq < 16; ++dq) {
            float4 wq4 = *(const float4*)(wqp + (dq << 7));
            float4 wk4 = *(const float4*)(wkp + (dq << 7));
            float4 wv4 = *(const float4*)(wvp + (dq << 7));
            #pragma unroll
            for (int j = 0; j < 4; ++j) {
                float wqv = (j == 0) ? wq4.x : (j == 1) ? wq4.y : (j == 2) ? wq4.z : wq4.w;
                float wkv = (j == 0) ? wk4.x : (j == 1) ? wk4.y : (j == 2) ? wk4.z : wk4.w;
                float wvv = (j == 0) ? wv4.x : (j == 1) ? wv4.y : (j == 2) ? wv4.z : wv4.w;
                ull w2q = pack2(wqv, wqv);
                ull w2k = pack2(wkv, wkv);
                ull w2v = pack2(wvv, wvv);
                const ulonglong2* xp = (const ulonglong2*)(xs + (dq << 6) + (j << 4));
                ulonglong2 xv0 = xp[0];
                ulonglong2 xv1 = xp[1];
                fma2(aq[0], w2q, xv0.x); fma2(aq[1], w2q, xv0.y);
                fma2(aq[2], w2q, xv1.x); fma2(aq[3], w2q, xv1.y);
                fma2(ak[0], w2k, xv0.x); fma2(ak[1], w2k, xv0.y);
                fma2(ak[2], w2k, xv1.x); fma2(ak[3], w2k, xv1.y);
                fma2(av[0], w2v, xv0.x); fma2(av[1], w2v, xv0.y);
                fma2(av[2], w2v, xv1.x); fma2(av[3], w2v, xv1.y);
                ulonglong2 xv2 = xp[2];
                ulonglong2 xv3 = xp[3];
                fma2(aq[4], w2q, xv2.x); fma2(aq[5], w2q, xv2.y);
                fma2(aq[6], w2q, xv3.x); fma2(aq[7], w2q, xv3.y);
                fma2(ak[4], w2k, xv2.x); fma2(ak[5], w2k, xv2.y);
                fma2(ak[6], w2k, xv3.x); fma2(ak[7], w2k, xv3.y);
                fma2(av[4], w2v, xv2.x); fma2(av[5], w2v, xv2.y);
                fma2(av[6], w2v, xv3.x); fma2(av[7], w2v, xv3.y);
            }
        }

        // ---- tanh; Q in regs, K/V to shared ----
        ull q2[8];
        #pragma unroll
        for (int p = 0; p < 8; ++p) {
            float a0, a1; unpack2(aq[p], a0, a1);
            q2[p] = pack2(fast_tanh(a0), fast_tanh(a1));
        }
        {
            float4* kp4 = (float4*)(ks + r * 20);
            float4* vp4 = (float4*)(vs + r * 20);
            #pragma unroll
            for (int p = 0; p < 4; ++p) {
                float a0, a1, a2, a3;
                unpack2(ak[2 * p], a0, a1); unpack2(ak[2 * p + 1], a2, a3);
                kp4[p] = make_float4(fast_tanh(a0), fast_tanh(a1), fast_tanh(a2), fast_tanh(a3));
                unpack2(av[2 * p], a0, a1); unpack2(av[2 * p + 1], a2, a3);
                vp4[p] = make_float4(fast_tanh(a0), fast_tanh(a1), fast_tanh(a2), fast_tanh(a3));
            }
        }
        __syncwarp();

        // ---- fused scores + o pass (no max-sub needed: |score| <= 16) ----
        ull o2[8];
        #pragma unroll
        for (int p = 0; p < 8; ++p) o2[p] = 0ull;
        float esum = 0.0f;
        #pragma unroll 8
        for (int s = 0; s < 32; ++s) {
            const ulonglong2* kp = (const ulonglong2*)(ks + s * 20);
            const ulonglong2* vp = (const ulonglong2*)(vs + s * 20);
            ulonglong2 k01 = kp[0], k23 = kp[1];
            ull acc = 0ull;
            fma2(acc, q2[0], k01.x); fma2(acc, q2[1], k01.y);
            fma2(acc, q2[2], k23.x); fma2(acc, q2[3], k23.y);
            ulonglong2 k45 = kp[2], k67 = kp[3];
            fma2(acc, q2[4], k45.x); fma2(acc, q2[5], k45.y);
            fma2(acc, q2[6], k67.x); fma2(acc, q2[7], k67.y);
            float lo, hi; unpack2(acc, lo, hi);
            float ev = exp2f((lo + hi) * scl2);
            esum += ev;
            ull e2 = pack2(ev, ev);
            ulonglong2 v01 = vp[0], v23 = vp[1];
            fma2(o2[0], e2, v01.x); fma2(o2[1], e2, v01.y);
            fma2(o2[2], e2, v23.x); fma2(o2[3], e2, v23.y);
            ulonglong2 v45 = vp[2], v67 = vp[3];
            fma2(o2[4], e2, v45.x); fma2(o2[5], e2, v45.y);
            fma2(o2[6], e2, v67.x); fma2(o2[7], e2, v67.y);
        }
        float inv = __fdividef(1.0f, esum);

        // ---- fold Ao[r]/esum_r, split-vector butterfly reduce ----
        {
            float aw = aoS[r] * inv;
            ull aw2 = pack2(aw, aw);
            #pragma unroll
            for (int p = 0; p < 8; ++p) {
                float a0, a1; unpack2(o2[p], a0, a1);
                o2[p] = pack2(a0 * aw, a1 * aw);
            }
            (void)aw2;
        }
        const bool b4 = (lane & 16) != 0;
        const bool b3 = (lane & 8)  != 0;
        const bool b2 = (lane & 4)  != 0;
        const bool b1 = (lane & 2)  != 0;
        // round 1 (xor 16): keep 4 ull
        ull k1[4];
        #pragma unroll
        for (int j = 0; j < 4; ++j) {
            ull send = b4 ? o2[j] : o2[4 + j];
            ull recv = __shfl_xor_sync(0xffffffffu, send, 16);
            k1[j] = add2(b4 ? o2[4 + j] : o2[j], recv);
        }
        // round 2 (xor 8): keep 2 ull
        ull k2r[2];
        #pragma unroll
        for (int j = 0; j < 2; ++j) {
            ull send = b3 ? k1[j] : k1[2 + j];
            ull recv = __shfl_xor_sync(0xffffffffu, send, 8);
            k2r[j] = add2(b3 ? k1[2 + j] : k1[j], recv);
        }
        // round 3 (xor 4): keep 1 ull
        ull k3;
        {
            ull send = b2 ? k2r[0] : k2r[1];
            ull recv = __shfl_xor_sync(0xffffffffu, send, 4);
            k3 = add2(b2 ? k2r[1] : k2r[0], recv);
        }
        // round 4 (xor 2): keep 1 float
        float c;
        {
            float lo, hi; unpack2(k3, lo, hi);
            float send = b1 ? lo : hi;
            float recv = __shfl_xor_sync(0xffffffffu, send, 2);
            c = (b1 ? hi : lo) + recv;
        }
        // round 5 (xor 1): lanes l and l^1 hold the same n
        c += __shfl_xor_sync(0xffffffffu, c, 1);
        // lane l now holds c[n], n = (l >> 1) & 15

        float t  = fast_tanh(c);
        float r2 = t * t;
        // rowsum: every n appears twice across the warp
        float rs = r2;
        #pragma unroll
        for (int off = 16; off > 0; off >>= 1)
            rs += __shfl_xor_sync(0xffffffffu, rs, off);
        rs *= 0.5f;

        if ((lane & 1) == 0) {
            int n = lane >> 1;
            int i = b & 15;
            out[(size_t)b * 16 + n] = (n == i) ? rs : -r2;
        }
        __syncwarp();
    }
}

extern "C" void kernel_launch(void* const* d_in, const int* in_sizes, int n_in,
                              void* d_out, int out_size) {
    const float* x  = (const float*)d_in[0];
    const float* L  = (const float*)d_in[1];
    const float* Aq = (const float*)d_in[2];
    const float* Ak = (const float*)d_in[3];
    const float* Av = (const float*)d_in[4];
    const float* Ao = (const float*)d_in[5];
    float* out = (float*)d_out;

    cudaFuncSetAttribute(att_mask_kernel,
                         cudaFuncAttributeMaxDynamicSharedMemorySize, SMEM_BYTES);
    att_mask_kernel<<<NBLOCKS, 256, SMEM_BYTES>>>(x, L, Aq, Ak, Av, Ao, out);
}

// round 4
// speedup vs baseline: 1.2271x; 1.0841x over previous
#include <cuda_runtime.h>

// Att_mask R4: fused low-rank tanh attention + Laplacian reconstruction.
// One warp per batch; lane = r. Packed f32x2 (FFMA2) math.
// New in R4:
//  * algebraic g-trick: c[n] = sum_s g[s] V[s,n], g[s] = sum_r (Ao_r/esum_r) e_rs
//    -> V stays in registers (no V broadcast, no V STS, o-accum GEMM removed)
//  * keep-own-bit split butterfly puts g[s] exactly at lane s (owner of V row s)
//  * cp.async.cg double-buffered x staging overlaps DRAM with phase 2

typedef unsigned long long ull;

#define WARPS_PER_BLOCK 8
#define ITERS 4
#define NBLOCKS 2048            // 2048 * 8 * 4 = 65536 batches
#define BSTRIDE (NBLOCKS * WARPS_PER_BLOCK)

__device__ __forceinline__ ull pack2(float lo, float hi) {
    ull r; asm("mov.b64 %0, {%1, %2};" : "=l"(r) : "f"(lo), "f"(hi)); return r;
}
__device__ __forceinline__ void unpack2(ull v, float& lo, float& hi) {
    asm("mov.b64 {%0, %1}, %2;" : "=f"(lo), "=f"(hi) : "l"(v));
}
__device__ __forceinline__ void fma2(ull& d, ull a, ull b) {
    asm("fma.rn.f32x2 %0, %1, %2, %0;" : "+l"(d) : "l"(a), "l"(b));
}
__device__ __forceinline__ ull mul2(ull a, ull b) {
    ull r; asm("mul.rn.f32x2 %0, %1, %2;" : "=l"(r) : "l"(a), "l"(b)); return r;
}
__device__ __forceinline__ ull add2(ull a, ull b) {
    ull r; asm("add.rn.f32x2 %0, %1, %2;" : "=l"(r) : "l"(a), "l"(b)); return r;
}
__device__ __forceinline__ float ex2f(float x) {           // guaranteed 1 MUFU
    float r; asm("ex2.approx.f32 %0, %1;" : "=f"(r) : "f"(x)); return r;
}
__device__ __forceinline__ float fast_tanh(float x) {      // 2 MUFU, rel err ~1e-6
    float e = ex2f(2.8853900817779268f * x);               // exp(2x) = 2^(2x*log2e)
    return 1.0f - __fdividef(2.0f, e + 1.0f);
}
__device__ __forceinline__ unsigned smem_u32(const void* p) {
    unsigned a;
    asm("{ .reg .u64 t; cvta.to.shared.u64 t, %1; cvt.u32.u64 %0, t; }" : "=r"(a) : "l"(p));
    return a;
}
__device__ __forceinline__ void cp_async16(unsigned dst, const void* src) {
    asm volatile("cp.async.cg.shared.global [%0], [%1], 16;" :: "r"(dst), "l"(src));
}
__device__ __forceinline__ void cp_commit() { asm volatile("cp.async.commit_group;"); }
__device__ __forceinline__ void cp_wait0()  { asm volatile("cp.async.wait_group 0;" ::: "memory"); }

// Shared (floats): wT [3][16dq][32r][4j] = 6144, aoS 32,
// per-warp: xsA 1024 | xsB 1024 | ks 32*20=640  -> 2688
#define PW_FLOATS   2688
#define SMEM_FLOATS (6144 + 32 + WARPS_PER_BLOCK * PW_FLOATS)
#define SMEM_BYTES  (SMEM_FLOATS * 4)

__global__ void __launch_bounds__(256) att_mask_kernel(
    const float* __restrict__ x, const float* __restrict__ L,
    const float* __restrict__ Aq, const float* __restrict__ Ak,
    const float* __restrict__ Av, const float* __restrict__ Ao,
    float* __restrict__ out)
{
    extern __shared__ float sm[];
    const int tid  = threadIdx.x;
    const int warp = tid >> 5;
    const int lane = tid & 31;

    float* wT  = sm;
    float* aoS = sm + 6144;
    float* wb  = sm + 6144 + 32 + warp * PW_FLOATS;
    float* xsA = wb;
    float* xsB = wb + 1024;
    float* ks  = wb + 2048;          // [32][20]

    // quad-packed weights: wT[mat*2048 + (d>>2)*128 + r*4 + (d&3)]
    for (int idx = tid; idx < 2048; idx += 256) {
        int r = idx >> 6, d = idx & 63;
        int off = ((d >> 2) << 7) + (r << 2) + (d & 3);
        wT[off]        = Aq[idx];
        wT[2048 + off] = Ak[idx];
        wT[4096 + off] = Av[idx];
    }
    if (tid < 32) aoS[tid] = Ao[tid];

    const int gw = blockIdx.x * WARPS_PER_BLOCK + warp;
    const int r  = lane;
    const float* wqp = wT + (r << 2);
    const float* wkp = wT + 2048 + (r << 2);
    const float* wvp = wT + 4096 + (r << 2);

    // prefetch x for it=0 into xsA; L element too
    {
        const char* xg0 = (const char*)(x + (size_t)gw * 1024);
        unsigned dstA = smem_u32(xsA);
        #pragma unroll
        for (int i = 0; i < 8; ++i)
            cp_async16(dstA + (i * 32 + lane) * 16, xg0 + (i * 32 + lane) * 16);
        cp_commit();
    }
    float lv_cur = (lane < 16) ? __ldg(L + (size_t)gw * 256 + lane) : 0.0f;
    __syncthreads();

    int buf = 0;
    for (int it = 0; it < ITERS; ++it) {
        const int b = gw + it * BSTRIDE;
        float* xs = buf ? xsB : xsA;

        cp_wait0();
        __syncwarp();

        // numNeighbors
        unsigned mb = __ballot_sync(0xffffffffu, lv_cur >= 1.0f);
        float scl2 = rsqrtf((float)(__popc(mb) + 1)) * 1.4426950408889634f;

        // ---- QKV projection ----
        ull aq[8], ak[8], av[8];
        #pragma unroll
        for (int p = 0; p < 8; ++p) { aq[p] = 0ull; ak[p] = 0ull; av[p] = 0ull; }

        #pragma unroll 4
        for (int dq = 0; dq < 16; ++dq) {
            float4 wq4 = *(const float4*)(wqp + (dq << 7));
            float4 wk4 = *(const float4*)(wkp + (dq << 7));
            float4 wv4 = *(const float4*)(wvp + (dq << 7));
            #pragma unroll
            for (int j = 0; j < 4; ++j) {
                float wqv = (j == 0) ? wq4.x : (j == 1) ? wq4.y : (j == 2) ? wq4.z : wq4.w;
                float wkv = (j == 0) ? wk4.x : (j == 1) ? wk4.y : (j == 2) ? wk4.z : wk4.w;
                float wvv = (j == 0) ? wv4.x : (j == 1) ? wv4.y : (j == 2) ? wv4.z : wv4.w;
                ull w2q = pack2(wqv, wqv);
                ull w2k = pack2(wkv, wkv);
                ull w2v = pack2(wvv, wvv);
                const ulonglong2* xp = (const ulonglong2*)(xs + (dq << 6) + (j << 4));
                ulonglong2 xv0 = xp[0], xv1 = xp[1];
                fma2(aq[0], w2q, xv0.x); fma2(aq[1], w2q, xv0.y);
                fma2(aq[2], w2q, xv1.x); fma2(aq[3], w2q, xv1.y);
                fma2(ak[0], w2k, xv0.x); fma2(ak[1], w2k, xv0.y);
                fma2(ak[2], w2k, xv1.x); fma2(ak[3], w2k, xv1.y);
                fma2(av[0], w2v, xv0.x); fma2(av[1], w2v, xv0.y);
                fma2(av[2], w2v, xv1.x); fma2(av[3], w2v, xv1.y);
                ulonglong2 xv2 = xp[2], xv3 = xp[3];
                fma2(aq[4], w2q, xv2.x); fma2(aq[5], w2q, xv2.y);
                fma2(aq[6], w2q, xv3.x); fma2(aq[7], w2q, xv3.y);
                fma2(ak[4], w2k, xv2.x); fma2(ak[5], w2k, xv2.y);
                fma2(ak[6], w2k, xv3.x); fma2(ak[7], w2k, xv3.y);
                fma2(av[4], w2v, xv2.x); fma2(av[5], w2v, xv2.y);
                fma2(av[6], w2v, xv3.x); fma2(av[7], w2v, xv3.y);
            }
        }

        // ---- prefetch next iteration's x / L (overlaps phase 2) ----
        {
            int itn = (it + 1 < ITERS) ? it + 1 : it;      // clamp: harmless refetch
            const int bn = gw + itn * BSTRIDE;
            const char* xgn = (const char*)(x + (size_t)bn * 1024);
            unsigned dstN = smem_u32(buf ? xsA : xsB);
            #pragma unroll
            for (int i = 0; i < 8; ++i)
                cp_async16(dstN + (i * 32 + lane) * 16, xgn + (i * 32 + lane) * 16);
            cp_commit();
            lv_cur = (lane < 16) ? __ldg(L + (size_t)bn * 256 + lane) : 0.0f;
        }

        // ---- tanh: Q, V in regs; K to shared ----
        ull q2[8], v2[8];
        #pragma unroll
        for (int p = 0; p < 8; ++p) {
            float a0, a1;
            unpack2(aq[p], a0, a1);
            q2[p] = pack2(fast_tanh(a0), fast_tanh(a1));
            unpack2(av[p], a0, a1);
            v2[p] = pack2(fast_tanh(a0), fast_tanh(a1));
        }
        {
            float4* kp4 = (float4*)(ks + r * 20);
            #pragma unroll
            for (int p = 0; p < 4; ++p) {
                float a0, a1, a2, a3;
                unpack2(ak[2 * p], a0, a1); unpack2(ak[2 * p + 1], a2, a3);
                kp4[p] = make_float4(fast_tanh(a0), fast_tanh(a1), fast_tanh(a2), fast_tanh(a3));
            }
        }
        __syncwarp();

        // ---- scores row r: e[r][s], esum (no max-sub: |score| <= 16) ----
        ull ep[16];                       // E[s] packed: ep[s>>1] = (e_{2sp}, e_{2sp+1})
        float esum = 0.0f;
        #pragma unroll 4
        for (int sp = 0; sp < 16; ++sp) {
            const ulonglong2* k0 = (const ulonglong2*)(ks + (2 * sp) * 20);
            const ulonglong2* k1 = (const ulonglong2*)(ks + (2 * sp + 1) * 20);
            ull acc0 = 0ull, acc1 = 0ull;
            ulonglong2 ka = k0[0], kb = k0[1], kc = k1[0], kd = k1[1];
            fma2(acc0, q2[0], ka.x); fma2(acc0, q2[1], ka.y);
            fma2(acc0, q2[2], kb.x); fma2(acc0, q2[3], kb.y);
            fma2(acc1, q2[0], kc.x); fma2(acc1, q2[1], kc.y);
            fma2(acc1, q2[2], kd.x); fma2(acc1, q2[3], kd.y);
            ka = k0[2]; kb = k0[3]; kc = k1[2]; kd = k1[3];
            fma2(acc0, q2[4], ka.x); fma2(acc0, q2[5], ka.y);
            fma2(acc0, q2[6], kb.x); fma2(acc0, q2[7], kb.y);
            fma2(acc1, q2[4], kc.x); fma2(acc1, q2[5], kc.y);
            fma2(acc1, q2[6], kd.x); fma2(acc1, q2[7], kd.y);
            float l0, h0, l1, h1;
            unpack2(acc0, l0, h0); unpack2(acc1, l1, h1);
            float e0 = ex2f((l0 + h0) * scl2);
            float e1 = ex2f((l1 + h1) * scl2);
            esum += e0 + e1;
            ep[sp] = pack2(e0, e1);
        }

        // ---- fold Ao[r]/esum_r into e-vector ----
        {
            float aw = aoS[r] * __fdividef(1.0f, esum);
            ull aw2 = pack2(aw, aw);
            #pragma unroll
            for (int sp = 0; sp < 16; ++sp) ep[sp] = mul2(ep[sp], aw2);
        }

        // ---- keep-own-bit split butterfly: g[s] lands at lane s ----
        // s-bit k comes from lane-bit k at round xor(1<<k).
        ull t8[8];
        #pragma unroll
        for (int j = 0; j < 8; ++j) {
            bool bb = (lane & 16) != 0;
            ull send = bb ? ep[j] : ep[8 + j];
            ull keep = bb ? ep[8 + j] : ep[j];
            t8[j] = add2(keep, __shfl_xor_sync(0xffffffffu, send, 16));
        }
        ull t4[4];
        #pragma unroll
        for (int j = 0; j < 4; ++j) {
            bool bb = (lane & 8) != 0;
            ull send = bb ? t8[j] : t8[4 + j];
            ull keep = bb ? t8[4 + j] : t8[j];
            t4[j] = add2(keep, __shfl_xor_sync(0xffffffffu, send, 8));
        }
        ull t2[2];
        #pragma unroll
        for (int j = 0; j < 2; ++j) {
            bool bb = (lane & 4) != 0;
            ull send = bb ? t4[j] : t4[2 + j];
            ull keep = bb ? t4[2 + j] : t4[j];
            t2[j] = add2(keep, __shfl_xor_sync(0xffffffffu, send, 4));
        }
        ull t1;
        {
            bool bb = (lane & 2) != 0;
            ull send = bb ? t2[0] : t2[1];
            ull keep = bb ? t2[1] : t2[0];
            t1 = add2(keep, __shfl_xor_sync(0xffffffffu, send, 2));
        }
        float g;
        {
            float lo, hi; unpack2(t1, lo, hi);
            bool bb = (lane & 1) != 0;
            float send = bb ? lo : hi;
            float keep = bb ? hi : lo;
            g = keep + __shfl_xor_sync(0xffffffffu, send, 1);
        }
        // lane s holds g[s]; this lane also owns V[s,:] in v2 — perfect match.

        // ---- c partial = g[s] * V[s,:], then split-reduce over 32 lanes ----
        ull pc[8];
        {
            ull g2 = pack2(g, g);
            #pragma unroll
            for (int p = 0; p < 8; ++p) pc[p] = mul2(g2, v2[p]);
        }
        const bool c4 = (lane & 16) != 0;
        const bool c3 = (lane & 8)  != 0;
        const bool c2 = (lane & 4)  != 0;
        const bool c1 = (lane & 2)  != 0;
        ull k1v[4];
        #pragma unroll
        for (int j = 0; j < 4; ++j) {
            ull send = c4 ? pc[j] : pc[4 + j];
            ull recv = __shfl_xor_sync(0xffffffffu, send, 16);
            k1v[j] = add2(c4 ? pc[4 + j] : pc[j], recv);
        }
        ull k2v[2];
        #pragma unroll
        for (int j = 0; j < 2; ++j) {
            ull send = c3 ? k1v[j] : k1v[2 + j];
            ull recv = __shfl_xor_sync(0xffffffffu, send, 8);
            k2v[j] = add2(c3 ? k1v[2 + j] : k1v[j], recv);
        }
        ull k3v;
        {
            ull send = c2 ? k2v[0] : k2v[1];
            ull recv = __shfl_xor_sync(0xffffffffu, send, 4);
            k3v = add2(c2 ? k2v[1] : k2v[0], recv);
        }
        float c;
        {
            float lo, hi; unpack2(k3v, lo, hi);
            float send = c1 ? lo : hi;
            float recv = __shfl_xor_sync(0xffffffffu, send, 2);
            c = (c1 ? hi : lo) + recv;
        }
        c += __shfl_xor_sync(0xffffffffu, c, 1);
        // lane l holds c[n], n = l>>1 (each n duplicated on lanes 2n, 2n+1)

        float t  = fast_tanh(c);
        float r2 = t * t;
        float rs = r2;
        #pragma unroll
        for (int off = 16; off > 0; off >>= 1)
            rs += __shfl_xor_sync(0xffffffffu, rs, off);
        rs *= 0.5f;

        if ((lane & 1) == 0) {
            int n = lane >> 1;
            int i = b & 15;
            out[(size_t)b * 16 + n] = (n == i) ? rs : -r2;
        }
        __syncwarp();
        buf ^= 1;
    }
}

extern "C" void kernel_launch(void* const* d_in, const int* in_sizes, int n_in,
                              void* d_out, int out_size) {
    const float* x  = (const float*)d_in[0];
    const float* L  = (const float*)d_in[1];
    const float* Aq = (const float*)d_in[2];
    const float* Ak = (const float*)d_in[3];
    const float* Av = (const float*)d_in[4];
    const float* Ao = (const float*)d_in[5];
    float* out = (float*)d_out;

    cudaFuncSetAttribute(att_mask_kernel,
                         cudaFuncAttributeMaxDynamicSharedMemorySize, SMEM_BYTES);
    att_mask_kernel<<<NBLOCKS, 256, SMEM_BYTES>>>(x, L, Aq, Ak, Av, Ao, out);
}

// round 7
// speedup vs baseline: 1.7637x; 1.4372x over previous
#include <cuda_runtime.h>
#include <cuda_bf16.h>
#include <cstdint>

// Att_mask R6: mma.sync (HMMA bf16, split-precision) projection + FFMA2 epilogue.
// tcgen05 is unavailable (harness lowers via compute_103 plain target), so the
// tensor path uses sm_80-era mma.sync.m16n8k16.bf16 + ldmatrix, which compile
// for plain sm_103 and run on the tensor pipe.
//
// One warp per batch. Per batch:
//   x[64][16] fp32 --LDG.128 coalesced--> regs --split bf16 hi/lo--> smem tiles
//   P[96][16] = (Whi+Wlo)@(xhi+xlo) via 3 terms x 48 mma.sync (m16n8k16)
//   C frags -> Pt[96][20] smem -> R4 attention epilogue (g-trick butterflies).

typedef unsigned long long ull;

#define THREADS 512
#define NCTAS   1024
#define ITERS   4            // 1024 CTAs * 16 warps * 4 = 65536 batches

// smem layout (bytes)
#define SM_WHI   0            // 96 rows x 128B bf16, SW128-chunk swizz
#define SM_WLO   12288
#define SM_WARP0 24576        // per-warp 7680B: [xhi 3072 | xlo 3072 | pad] / Pt overlay
#define PW_BYTES 7680
#define SM_AO    (SM_WARP0 + 16 * PW_BYTES)      // 147456
#define SMEM_BYTES (SM_AO + 128)

#define PT_STRIDE 20          // floats
#define XROW_B    48          // x bf16 tile row stride bytes (conflict-free LDSM)

// ---------------- packed f32x2 helpers ----------------
__device__ __forceinline__ ull pack2(float lo, float hi) {
    ull r; asm("mov.b64 %0, {%1, %2};" : "=l"(r) : "f"(lo), "f"(hi)); return r;
}
__device__ __forceinline__ void unpack2(ull v, float& lo, float& hi) {
    asm("mov.b64 {%0, %1}, %2;" : "=f"(lo), "=f"(hi) : "l"(v));
}
__device__ __forceinline__ void fma2(ull& d, ull a, ull b) {
    asm("fma.rn.f32x2 %0, %1, %2, %0;" : "+l"(d) : "l"(a), "l"(b));
}
__device__ __forceinline__ ull mul2(ull a, ull b) {
    ull r; asm("mul.rn.f32x2 %0, %1, %2;" : "=l"(r) : "l"(a), "l"(b)); return r;
}
__device__ __forceinline__ ull add2(ull a, ull b) {
    ull r; asm("add.rn.f32x2 %0, %1, %2;" : "=l"(r) : "l"(a), "l"(b)); return r;
}
__device__ __forceinline__ float ex2f(float x) {
    float r; asm("ex2.approx.f32 %0, %1;" : "=f"(r) : "f"(x)); return r;
}
__device__ __forceinline__ float fast_tanh(float x) {      // 1-2/(e^2x+1), ~1e-6
    float e = ex2f(2.8853900817779268f * x);
    return 1.0f - __fdividef(2.0f, e + 1.0f);
}

// ---------------- smem / mma helpers ----------------
__device__ __forceinline__ unsigned smem_u32(const void* p) {
    unsigned a;
    asm("{ .reg .u64 t; cvta.to.shared.u64 t, %1; cvt.u32.u64 %0, t; }" : "=r"(a) : "l"(p));
    return a;
}
__device__ __forceinline__ unsigned cvtpack2(float lo, float hi) {
    // d = {high-half = first src, low-half = second src}
    unsigned r; asm("cvt.rn.bf16x2.f32 %0, %1, %2;" : "=r"(r) : "f"(hi), "f"(lo)); return r;
}
__device__ __forceinline__ void ldsm_x4(unsigned r[4], unsigned addr) {
    asm volatile("ldmatrix.sync.aligned.m8n8.x4.shared.b16 {%0,%1,%2,%3}, [%4];"
                 : "=r"(r[0]), "=r"(r[1]), "=r"(r[2]), "=r"(r[3]) : "r"(addr));
}
__device__ __forceinline__ void ldsm_x4_t(unsigned r[4], unsigned addr) {
    asm volatile("ldmatrix.sync.aligned.m8n8.x4.trans.shared.b16 {%0,%1,%2,%3}, [%4];"
                 : "=r"(r[0]), "=r"(r[1]), "=r"(r[2]), "=r"(r[3]) : "r"(addr));
}
__device__ __forceinline__ void mma_bf16(float* c, const unsigned* a, const unsigned* b) {
    asm volatile("mma.sync.aligned.m16n8k16.row.col.f32.bf16.bf16.f32 "
                 "{%0,%1,%2,%3}, {%4,%5,%6,%7}, {%8,%9}, {%0,%1,%2,%3};"
                 : "+f"(c[0]), "+f"(c[1]), "+f"(c[2]), "+f"(c[3])
                 : "r"(a[0]), "r"(a[1]), "r"(a[2]), "r"(a[3]), "r"(b[0]), "r"(b[1]));
}
__device__ __forceinline__ void sts_v2(unsigned addr, unsigned a, unsigned b) {
    asm volatile("st.shared.v2.b32 [%0], {%1, %2};" :: "r"(addr), "r"(a), "r"(b));
}

__global__ void __launch_bounds__(THREADS, 1) att_mask_kernel(
    const float* __restrict__ x, const float* __restrict__ L,
    const float* __restrict__ Aq, const float* __restrict__ Ak,
    const float* __restrict__ Av, const float* __restrict__ Ao,
    float* __restrict__ out)
{
    extern __shared__ char smem[];
    const int tid  = threadIdx.x;
    const int warp = tid >> 5;
    const int lane = tid & 31;
    const unsigned smem_base = smem_u32(smem);

    // ---- stage W split-bf16, chunk-swizzled [96 rows][128B] ----
    for (int idx = tid; idx < 6144; idx += THREADS) {
        int row = idx >> 6, d = idx & 63;
        float val = (row < 32) ? Aq[row * 64 + d]
                  : (row < 64) ? Ak[(row - 32) * 64 + d]
                               : Av[(row - 64) * 64 + d];
        __nv_bfloat16 h = __float2bfloat16(val);
        __nv_bfloat16 l = __float2bfloat16(val - __bfloat162float(h));
        int off = row * 128 + (((d >> 3) ^ (row & 7)) << 4) + (d & 7) * 2;
        *(__nv_bfloat16*)(smem + SM_WHI + off) = h;
        *(__nv_bfloat16*)(smem + SM_WLO + off) = l;
    }
    float* aoS = (float*)(smem + SM_AO);
    if (tid < 32) aoS[tid] = Ao[tid];
    __syncthreads();

    // per-warp regions
    const unsigned xhib = smem_base + SM_WARP0 + warp * PW_BYTES;
    const unsigned xlob = xhib + 3072;
    float* Pt = (float*)(smem + SM_WARP0 + warp * PW_BYTES);   // overlays tiles

    // ldmatrix lane addressing (constant per lane)
    const int lm  = lane >> 3;          // matrix id within x4
    const int li  = lane & 7;           // row within matrix
    // A (W) tiles: row-major m16k16, swizzled chunks
    const unsigned a_row  = ((lm & 1) << 3) + li;      // 0..15 local m
    const unsigned a_cb   = (unsigned)(lm >> 1);       // k-chunk within tile
    // B (x) tiles: [k][n] rows of 48B, trans load
    const unsigned b_roff = (((lm & 1) << 3) + li) * XROW_B + ((lm >> 1) << 4);

    const int gw = blockIdx.x * 16 + warp;

    for (int it = 0; it < ITERS; ++it) {
        const int b = gw * ITERS + it;

        // ---- load x coalesced + L ----
        const float4* xg4 = (const float4*)(x + (size_t)b * 1024);
        float4 xv[8];
        #pragma unroll
        for (int j = 0; j < 8; ++j) xv[j] = xg4[j * 32 + lane];
        float lv = (lane < 16) ? __ldg(L + (size_t)b * 256 + lane) : 0.0f;

        __syncwarp();    // prior epilogue reads of Pt done before tile overwrite

        // ---- convert to bf16 hi/lo tiles [d=64][n=16], rows 48B ----
        #pragma unroll
        for (int j = 0; j < 8; ++j) {
            float4 v = xv[j];
            unsigned h01 = cvtpack2(v.x, v.y);
            unsigned h23 = cvtpack2(v.z, v.w);
            float f0 = __uint_as_float(h01 << 16);
            float f1 = __uint_as_float(h01 & 0xffff0000u);
            float f2 = __uint_as_float(h23 << 16);
            float f3 = __uint_as_float(h23 & 0xffff0000u);
            unsigned l01 = cvtpack2(v.x - f0, v.y - f1);
            unsigned l23 = cvtpack2(v.z - f2, v.w - f3);
            unsigned off = (unsigned)((8 * j + (lane >> 2)) * XROW_B + (lane & 3) * 8);
            sts_v2(xhib + off, h01, h23);
            sts_v2(xlob + off, l01, l23);
        }
        __syncwarp();

        // ---- projection: 3 terms x (6 mt x 2 nt x 4 kt) mma.sync ----
        float acc[6][8];
        #pragma unroll
        for (int mt = 0; mt < 6; ++mt)
            #pragma unroll
            for (int p = 0; p < 8; ++p) acc[mt][p] = 0.0f;

        #pragma unroll
        for (int kt = 0; kt < 4; ++kt) {
            unsigned bh[4], bl[4];
            unsigned boff = (unsigned)(kt * 16 * XROW_B) + b_roff;
            ldsm_x4_t(bh, xhib + boff);
            ldsm_x4_t(bl, xlob + boff);
            unsigned ach = (((kt * 2 + a_cb) ^ li) << 4);
            #pragma unroll
            for (int mt = 0; mt < 6; ++mt) {
                unsigned ah[4], al[4];
                unsigned arow = (unsigned)(mt * 16 + a_row) * 128 + ach;
                ldsm_x4(ah, smem_base + SM_WHI + arow);
                ldsm_x4(al, smem_base + SM_WLO + arow);
                mma_bf16(acc[mt] + 0, ah, bh + 0);
                mma_bf16(acc[mt] + 4, ah, bh + 2);
                mma_bf16(acc[mt] + 0, ah, bl + 0);
                mma_bf16(acc[mt] + 4, ah, bl + 2);
                mma_bf16(acc[mt] + 0, al, bh + 0);
                mma_bf16(acc[mt] + 4, al, bh + 2);
            }
        }

        // ---- C frags -> Pt[96][20] ----
        {
            int g  = lane >> 2;
            int tg = lane & 3;
            #pragma unroll
            for (int mt = 0; mt < 6; ++mt) {
                #pragma unroll
                for (int nt = 0; nt < 2; ++nt) {
                    const float* c = acc[mt] + nt * 4;
                    int col = nt * 8 + tg * 2;
                    float* p0 = Pt + (mt * 16 + g) * PT_STRIDE + col;
                    float* p1 = Pt + (mt * 16 + g + 8) * PT_STRIDE + col;
                    *(float2*)p0 = make_float2(c[0], c[1]);
                    *(float2*)p1 = make_float2(c[2], c[3]);
                }
            }
        }
        __syncwarp();

        // ================= attention epilogue (R4, proven) =================
        {
            const int r = lane;
            unsigned mbal = __ballot_sync(0xffffffffu, lv >= 1.0f);
            float scl2 = rsqrtf((float)(__popc(mbal) + 1)) * 1.4426950408889634f;

            // Q,V lane-private rows (tanh applied here)
            ull q2[8], v2[8];
            {
                const float* qrow = Pt + r * PT_STRIDE;
                const float* vrow = Pt + (64 + r) * PT_STRIDE;
                #pragma unroll
                for (int i = 0; i < 4; ++i) {
                    float4 qv = *(const float4*)(qrow + 4 * i);
                    float4 vv = *(const float4*)(vrow + 4 * i);
                    q2[2*i]   = pack2(fast_tanh(qv.x), fast_tanh(qv.y));
                    q2[2*i+1] = pack2(fast_tanh(qv.z), fast_tanh(qv.w));
                    v2[2*i]   = pack2(fast_tanh(vv.x), fast_tanh(vv.y));
                    v2[2*i+1] = pack2(fast_tanh(vv.z), fast_tanh(vv.w));
                }
            }
            // K rows: tanh into per-lane smem row? K must be tanh'd too.
            // Write tanh(K row r) back into Pt row 32+r (lane-private), then sync.
            {
                float* krow = Pt + (32 + r) * PT_STRIDE;
                #pragma unroll
                for (int i = 0; i < 4; ++i) {
                    float4 kv = *(const float4*)(krow + 4 * i);
                    kv.x = fast_tanh(kv.x); kv.y = fast_tanh(kv.y);
                    kv.z = fast_tanh(kv.z); kv.w = fast_tanh(kv.w);
                    *(float4*)(krow + 4 * i) = kv;
                }
            }
            __syncwarp();

            // scores row r over all s (K broadcast); |score| <= 16, no max-sub
            ull ep[16];
            float esum = 0.0f;
            #pragma unroll 4
            for (int sp = 0; sp < 16; ++sp) {
                const ulonglong2* k0 = (const ulonglong2*)(Pt + (32 + 2 * sp) * PT_STRIDE);
                const ulonglong2* k1 = (const ulonglong2*)(Pt + (33 + 2 * sp) * PT_STRIDE);
                ull acc0 = 0ull, acc1 = 0ull;
                ulonglong2 ka = k0[0], kb = k0[1], kc = k1[0], kd = k1[1];
                fma2(acc0, q2[0], ka.x); fma2(acc0, q2[1], ka.y);
                fma2(acc0, q2[2], kb.x); fma2(acc0, q2[3], kb.y);
                fma2(acc1, q2[0], kc.x); fma2(acc1, q2[1], kc.y);
                fma2(acc1, q2[2], kd.x); fma2(acc1, q2[3], kd.y);
                ka = k0[2]; kb = k0[3]; kc = k1[2]; kd = k1[3];
                fma2(acc0, q2[4], ka.x); fma2(acc0, q2[5], ka.y);
                fma2(acc0, q2[6], kb.x); fma2(acc0, q2[7], kb.y);
                fma2(acc1, q2[4], kc.x); fma2(acc1, q2[5], kc.y);
                fma2(acc1, q2[6], kd.x); fma2(acc1, q2[7], kd.y);
                float l0, h0, l1, h1;
                unpack2(acc0, l0, h0); unpack2(acc1, l1, h1);
                float e0 = ex2f((l0 + h0) * scl2);
                float e1 = ex2f((l1 + h1) * scl2);
                esum += e0 + e1;
                ep[sp] = pack2(e0, e1);
            }
            {
                float aw = aoS[r] * __fdividef(1.0f, esum);
                ull aw2 = pack2(aw, aw);
                #pragma unroll
                for (int sp = 0; sp < 16; ++sp) ep[sp] = mul2(ep[sp], aw2);
            }

            // keep-own-bit butterfly: g[s] lands at lane s
            ull t8[8];
            #pragma unroll
            for (int j = 0; j < 8; ++j) {
                bool bb = (lane & 16) != 0;
                ull send = bb ? ep[j] : ep[8 + j];
                ull keep = bb ? ep[8 + j] : ep[j];
                t8[j] = add2(keep, __shfl_xor_sync(0xffffffffu, send, 16));
            }
            ull t4[4];
            #pragma unroll
            for (int j = 0; j < 4; ++j) {
                bool bb = (lane & 8) != 0;
                ull send = bb ? t8[j] : t8[4 + j];
                ull keep = bb ? t8[4 + j] : t8[j];
                t4[j] = add2(keep, __shfl_xor_sync(0xffffffffu, send, 8));
            }
            ull t2[2];
            #pragma unroll
            for (int j = 0; j < 2; ++j) {
                bool bb = (lane & 4) != 0;
                ull send = bb ? t4[j] : t4[2 + j];
                ull keep = bb ? t4[2 + j] : t4[j];
                t2[j] = add2(keep, __shfl_xor_sync(0xffffffffu, send, 4));
            }
            ull t1;
            {
                bool bb = (lane & 2) != 0;
                ull send = bb ? t2[0] : t2[1];
                ull keep = bb ? t2[1] : t2[0];
                t1 = add2(keep, __shfl_xor_sync(0xffffffffu, send, 2));
            }
            float g;
            {
                float lo, hi; unpack2(t1, lo, hi);
                bool bb = (lane & 1) != 0;
                float send = bb ? lo : hi;
                float keep = bb ? hi : lo;
                g = keep + __shfl_xor_sync(0xffffffffu, send, 1);
            }

            // c = sum_s g[s] * V[s,:]
            ull pc[8];
            {
                ull g2 = pack2(g, g);
                #pragma unroll
                for (int p = 0; p < 8; ++p) pc[p] = mul2(g2, v2[p]);
            }
            const bool c4 = (lane & 16) != 0;
            const bool c3 = (lane & 8)  != 0;
            const bool c2 = (lane & 4)  != 0;
            const bool c1 = (lane & 2)  != 0;
            ull k1v[4];
            #pragma unroll
            for (int j = 0; j < 4; ++j) {
                ull send = c4 ? pc[j] : pc[4 + j];
                k1v[j] = add2(c4 ? pc[4 + j] : pc[j],
                              __shfl_xor_sync(0xffffffffu, send, 16));
            }
            ull k2v[2];
            #pragma unroll
            for (int j = 0; j < 2; ++j) {
                ull send = c3 ? k1v[j] : k1v[2 + j];
                k2v[j] = add2(c3 ? k1v[2 + j] : k1v[j],
                              __shfl_xor_sync(0xffffffffu, send, 8));
            }
            ull k3v;
            {
                ull send = c2 ? k2v[0] : k2v[1];
                k3v = add2(c2 ? k2v[1] : k2v[0],
                           __shfl_xor_sync(0xffffffffu, send, 4));
            }
            float cval;
            {
                float lo, hi; unpack2(k3v, lo, hi);
                float send = c1 ? lo : hi;
                cval = (c1 ? hi : lo) + __shfl_xor_sync(0xffffffffu, send, 2);
            }
            cval += __shfl_xor_sync(0xffffffffu, cval, 1);

            float t  = fast_tanh(cval);
            float r2 = t * t;
            float rs = r2;
            #pragma unroll
            for (int off = 16; off > 0; off >>= 1)
                rs += __shfl_xor_sync(0xffffffffu, rs, off);
            rs *= 0.5f;

            if ((lane & 1) == 0) {
                int n = lane >> 1;
                int i = b & 15;
                out[(size_t)b * 16 + n] = (n == i) ? rs : -r2;
            }
        }
        __syncwarp();
    }
}

extern "C" void kernel_launch(void* const* d_in, const int* in_sizes, int n_in,
                              void* d_out, int out_size) {
    const float* x  = (const float*)d_in[0];
    const float* L  = (const float*)d_in[1];
    const float* Aq = (const float*)d_in[2];
    const float* Ak = (const float*)d_in[3];
    const float* Av = (const float*)d_in[4];
    const float* Ao = (const float*)d_in[5];
    float* out = (float*)d_out;

    cudaFuncSetAttribute(att_mask_kernel,
                         cudaFuncAttributeMaxDynamicSharedMemorySize, SMEM_BYTES);
    att_mask_kernel<<<NCTAS, THREADS, SMEM_BYTES>>>(x, L, Aq, Ak, Av, Ao, out);
}

// round 9
// speedup vs baseline: 2.3822x; 1.3507x over previous
#include <cuda_runtime.h>
#include <cuda_bf16.h>
#include <cstdint>

// Att_mask R8: fully register-resident pipeline.
//   proj P[96][16] = W@x via split-bf16 mma.sync (R6, proven)
//   tanh on C fragments (in regs)
//   scores[32][32] = Qt@Kt^T via mma.sync with A/B fragments built IN REGISTERS
//     from the projection C fragments (n=16==k=16 layout identity; no smem)
//   softmax + g-trick + V contraction via quad/octet shuffle reductions
// Per-batch smem traffic: only x staging (16 STS + 8 LDSM) + W LDSM.

typedef unsigned long long ull;

#define THREADS 512
#define NCTAS   1024
#define ITERS   4            // 1024 * 16 warps * 4 = 65536 batches

#define SM_WHI   0           // 96 rows x 128B bf16, chunk-swizzled
#define SM_WLO   12288
#define SM_WARP0 24576
#define PW_BYTES 6144        // per-warp: xhi 3072 | xlo 3072
#define SMEM_BYTES (SM_WARP0 + 16 * PW_BYTES + 128)

#define XROW_B   48          // x bf16 tile row stride (conflict-free LDSM.trans)

// ---------------- packed f32x2 helpers ----------------
__device__ __forceinline__ ull pack2(float lo, float hi) {
    ull r; asm("mov.b64 %0, {%1, %2};" : "=l"(r) : "f"(lo), "f"(hi)); return r;
}
__device__ __forceinline__ void unpack2(ull v, float& lo, float& hi) {
    asm("mov.b64 {%0, %1}, %2;" : "=f"(lo), "=f"(hi) : "l"(v));
}
__device__ __forceinline__ void fma2(ull& d, ull a, ull b) {
    asm("fma.rn.f32x2 %0, %1, %2, %0;" : "+l"(d) : "l"(a), "l"(b));
}
__device__ __forceinline__ ull add2(ull a, ull b) {
    ull r; asm("add.rn.f32x2 %0, %1, %2;" : "=l"(r) : "l"(a), "l"(b)); return r;
}
__device__ __forceinline__ float ex2f(float x) {
    float r; asm("ex2.approx.f32 %0, %1;" : "=f"(r) : "f"(x)); return r;
}
__device__ __forceinline__ float fast_tanh(float x) {      // 1-2/(e^2x+1), ~1e-6
    float e = ex2f(2.8853900817779268f * x);
    return 1.0f - __fdividef(2.0f, e + 1.0f);
}

// ---------------- smem / mma helpers ----------------
__device__ __forceinline__ unsigned smem_u32(const void* p) {
    unsigned a;
    asm("{ .reg .u64 t; cvta.to.shared.u64 t, %1; cvt.u32.u64 %0, t; }" : "=r"(a) : "l"(p));
    return a;
}
__device__ __forceinline__ unsigned cvtpack2(float lo, float hi) {
    unsigned r; asm("cvt.rn.bf16x2.f32 %0, %1, %2;" : "=r"(r) : "f"(hi), "f"(lo)); return r;
}
// split (a,b) into bf16x2 hi pair + residual lo pair
__device__ __forceinline__ void split_pair(float a, float b, unsigned& hi, unsigned& lo) {
    hi = cvtpack2(a, b);
    float ha = __uint_as_float(hi << 16);
    float hb = __uint_as_float(hi & 0xffff0000u);
    lo = cvtpack2(a - ha, b - hb);
}
__device__ __forceinline__ void ldsm_x4(unsigned r[4], unsigned addr) {
    asm volatile("ldmatrix.sync.aligned.m8n8.x4.shared.b16 {%0,%1,%2,%3}, [%4];"
                 : "=r"(r[0]), "=r"(r[1]), "=r"(r[2]), "=r"(r[3]) : "r"(addr));
}
__device__ __forceinline__ void ldsm_x4_t(unsigned r[4], unsigned addr) {
    asm volatile("ldmatrix.sync.aligned.m8n8.x4.trans.shared.b16 {%0,%1,%2,%3}, [%4];"
                 : "=r"(r[0]), "=r"(r[1]), "=r"(r[2]), "=r"(r[3]) : "r"(addr));
}
__device__ __forceinline__ void mma_bf16(float* c, const unsigned* a, const unsigned* b) {
    asm volatile("mma.sync.aligned.m16n8k16.row.col.f32.bf16.bf16.f32 "
                 "{%0,%1,%2,%3}, {%4,%5,%6,%7}, {%8,%9}, {%0,%1,%2,%3};"
                 : "+f"(c[0]), "+f"(c[1]), "+f"(c[2]), "+f"(c[3])
                 : "r"(a[0]), "r"(a[1]), "r"(a[2]), "r"(a[3]), "r"(b[0]), "r"(b[1]));
}
__device__ __forceinline__ void sts_v2(unsigned addr, unsigned a, unsigned b) {
    asm volatile("st.shared.v2.b32 [%0], {%1, %2};" :: "r"(addr), "r"(a), "r"(b));
}

__global__ void __launch_bounds__(THREADS, 1) att_mask_kernel(
    const float* __restrict__ x, const float* __restrict__ L,
    const float* __restrict__ Aq, const float* __restrict__ Ak,
    const float* __restrict__ Av, const float* __restrict__ Ao,
    float* __restrict__ out)
{
    extern __shared__ char smem[];
    const int tid  = threadIdx.x;
    const int warp = tid >> 5;
    const int lane = tid & 31;
    const int g    = lane >> 2;          // fragment group (row)
    const int tg   = lane & 3;           // thread-in-group (col pair)
    const unsigned smem_base = smem_u32(smem);

    // ---- stage W split-bf16, chunk-swizzled [96 rows][128B] (R6, proven) ----
    for (int idx = tid; idx < 6144; idx += THREADS) {
        int row = idx >> 6, d = idx & 63;
        float val = (row < 32) ? Aq[row * 64 + d]
                  : (row < 64) ? Ak[(row - 32) * 64 + d]
                               : Av[(row - 64) * 64 + d];
        __nv_bfloat16 h = __float2bfloat16(val);
        __nv_bfloat16 l = __float2bfloat16(val - __bfloat162float(h));
        int off = row * 128 + (((d >> 3) ^ (row & 7)) << 4) + (d & 7) * 2;
        *(__nv_bfloat16*)(smem + SM_WHI + off) = h;
        *(__nv_bfloat16*)(smem + SM_WLO + off) = l;
    }
    // hoist Ao rows this lane will ever need (rows g+8j)
    float aoR0 = __ldg(Ao + g);
    float aoR1 = __ldg(Ao + g + 8);
    float aoR2 = __ldg(Ao + g + 16);
    float aoR3 = __ldg(Ao + g + 24);
    __syncthreads();

    const unsigned xhib = smem_base + SM_WARP0 + warp * PW_BYTES;
    const unsigned xlob = xhib + 3072;

    // ldmatrix lane addressing (R6, proven)
    const int lm = lane >> 3;
    const int li = lane & 7;
    const unsigned a_row  = ((lm & 1) << 3) + li;
    const unsigned a_cb   = (unsigned)(lm >> 1);
    const unsigned b_roff = (((lm & 1) << 3) + li) * XROW_B + ((lm >> 1) << 4);

    const int gw = blockIdx.x * 16 + warp;

    for (int it = 0; it < ITERS; ++it) {
        const int b = gw * ITERS + it;

        // ---- load x coalesced + L ----
        const float4* xg4 = (const float4*)(x + (size_t)b * 1024);
        float4 xv[8];
        #pragma unroll
        for (int j = 0; j < 8; ++j) xv[j] = xg4[j * 32 + lane];
        float lv = (lane < 16) ? __ldg(L + (size_t)b * 256 + lane) : 0.0f;

        __syncwarp();

        // ---- convert x to bf16 hi/lo tiles [d=64][n=16], rows 48B ----
        #pragma unroll
        for (int j = 0; j < 8; ++j) {
            float4 v = xv[j];
            unsigned h01 = cvtpack2(v.x, v.y);
            unsigned h23 = cvtpack2(v.z, v.w);
            float f0 = __uint_as_float(h01 << 16);
            float f1 = __uint_as_float(h01 & 0xffff0000u);
            float f2 = __uint_as_float(h23 << 16);
            float f3 = __uint_as_float(h23 & 0xffff0000u);
            unsigned l01 = cvtpack2(v.x - f0, v.y - f1);
            unsigned l23 = cvtpack2(v.z - f2, v.w - f3);
            unsigned off = (unsigned)((8 * j + (lane >> 2)) * XROW_B + (lane & 3) * 8);
            sts_v2(xhib + off, h01, h23);
            sts_v2(xlob + off, l01, l23);
        }
        __syncwarp();

        // ---- projection: 3 terms x (6 mt x 2 nt x 4 kt) mma.sync (R6) ----
        float acc[6][8];
        #pragma unroll
        for (int mt = 0; mt < 6; ++mt)
            #pragma unroll
            for (int p = 0; p < 8; ++p) acc[mt][p] = 0.0f;

        #pragma unroll
        for (int kt = 0; kt < 4; ++kt) {
            unsigned bh[4], bl[4];
            unsigned boff = (unsigned)(kt * 16 * XROW_B) + b_roff;
            ldsm_x4_t(bh, xhib + boff);
            ldsm_x4_t(bl, xlob + boff);
            unsigned ach = (((kt * 2 + a_cb) ^ li) << 4);
            #pragma unroll
            for (int mt = 0; mt < 6; ++mt) {
                unsigned ah[4], al[4];
                unsigned arow = (unsigned)(mt * 16 + a_row) * 128 + ach;
                ldsm_x4(ah, smem_base + SM_WHI + arow);
                ldsm_x4(al, smem_base + SM_WLO + arow);
                mma_bf16(acc[mt] + 0, ah, bh + 0);
                mma_bf16(acc[mt] + 4, ah, bh + 2);
                mma_bf16(acc[mt] + 0, ah, bl + 0);
                mma_bf16(acc[mt] + 4, ah, bl + 2);
                mma_bf16(acc[mt] + 0, al, bh + 0);
                mma_bf16(acc[mt] + 4, al, bh + 2);
            }
        }

        // ---- tanh on all fragments (Q,K,V in regs) ----
        #pragma unroll
        for (int mt = 0; mt < 6; ++mt)
            #pragma unroll
            for (int p = 0; p < 8; ++p) acc[mt][p] = fast_tanh(acc[mt][p]);

        // ---- numNeighbors scale ----
        unsigned mbal = __ballot_sync(0xffffffffu, lv >= 1.0f);
        float scl2 = rsqrtf((float)(__popc(mbal) + 1)) * 1.4426950408889634f;

        // ---- K B-fragments (hi/lo) straight from C fragments ----
        // nt' s-tile base 8*nt': b0,b1 pairs are direct acc pairs (layout identity)
        unsigned kbh[4][2], kbl[4][2];
        split_pair(acc[2][0], acc[2][1], kbh[0][0], kbl[0][0]);
        split_pair(acc[2][4], acc[2][5], kbh[0][1], kbl[0][1]);
        split_pair(acc[2][2], acc[2][3], kbh[1][0], kbl[1][0]);
        split_pair(acc[2][6], acc[2][7], kbh[1][1], kbl[1][1]);
        split_pair(acc[3][0], acc[3][1], kbh[2][0], kbl[2][0]);
        split_pair(acc[3][4], acc[3][5], kbh[2][1], kbl[2][1]);
        split_pair(acc[3][2], acc[3][3], kbh[3][0], kbl[3][0]);
        split_pair(acc[3][6], acc[3][7], kbh[3][1], kbl[3][1]);

        // ---- scores = Qt @ Kt^T : 2 mt' x 4 nt' x 3 terms mma ----
        float sc[2][16];
        #pragma unroll
        for (int m = 0; m < 2; ++m)
            #pragma unroll
            for (int p = 0; p < 16; ++p) sc[m][p] = 0.0f;

        #pragma unroll
        for (int m = 0; m < 2; ++m) {
            unsigned qh[4], ql[4];
            split_pair(acc[m][0], acc[m][1], qh[0], ql[0]);
            split_pair(acc[m][2], acc[m][3], qh[1], ql[1]);
            split_pair(acc[m][4], acc[m][5], qh[2], ql[2]);
            split_pair(acc[m][6], acc[m][7], qh[3], ql[3]);
            #pragma unroll
            for (int nt = 0; nt < 4; ++nt) {
                mma_bf16(sc[m] + nt * 4, qh, kbh[nt]);
                mma_bf16(sc[m] + nt * 4, qh, kbl[nt]);
                mma_bf16(sc[m] + nt * 4, ql, kbh[nt]);
            }
        }

        // ---- e = exp2(score * scl2) in place ----
        #pragma unroll
        for (int m = 0; m < 2; ++m)
            #pragma unroll
            for (int p = 0; p < 16; ++p) sc[m][p] = ex2f(sc[m][p] * scl2);

        // ---- esum per row (rows g, g+8, 16+g, 24+g); reduce over quad ----
        float rA0 = 0.0f, rA1 = 0.0f, rB0 = 0.0f, rB1 = 0.0f;
        #pragma unroll
        for (int nt = 0; nt < 4; ++nt) {
            rA0 += sc[0][nt * 4 + 0] + sc[0][nt * 4 + 1];
            rA1 += sc[0][nt * 4 + 2] + sc[0][nt * 4 + 3];
            rB0 += sc[1][nt * 4 + 0] + sc[1][nt * 4 + 1];
            rB1 += sc[1][nt * 4 + 2] + sc[1][nt * 4 + 3];
        }
        ull u0 = pack2(rA0, rA1), u1 = pack2(rB0, rB1);
        u0 = add2(u0, __shfl_xor_sync(0xffffffffu, u0, 1));
        u0 = add2(u0, __shfl_xor_sync(0xffffffffu, u0, 2));
        u1 = add2(u1, __shfl_xor_sync(0xffffffffu, u1, 1));
        u1 = add2(u1, __shfl_xor_sync(0xffffffffu, u1, 2));
        float es0, es1, es2, es3;
        unpack2(u0, es0, es1); unpack2(u1, es2, es3);
        float w0 = aoR0 * __fdividef(1.0f, es0);
        float w1 = aoR1 * __fdividef(1.0f, es1);
        float w2 = aoR2 * __fdividef(1.0f, es2);
        float w3 = aoR3 * __fdividef(1.0f, es3);

        // ---- g[s] = sum_r w[r] e[r][s]; reduce over g-lanes (xor 4,8,16) ----
        ull w00 = pack2(w0, w0), w11 = pack2(w1, w1);
        ull w22 = pack2(w2, w2), w33 = pack2(w3, w3);
        ull gp[4];
        #pragma unroll
        for (int nt = 0; nt < 4; ++nt) {
            ull a = 0ull;
            fma2(a, w00, pack2(sc[0][nt * 4 + 0], sc[0][nt * 4 + 1]));
            fma2(a, w11, pack2(sc[0][nt * 4 + 2], sc[0][nt * 4 + 3]));
            fma2(a, w22, pack2(sc[1][nt * 4 + 0], sc[1][nt * 4 + 1]));
            fma2(a, w33, pack2(sc[1][nt * 4 + 2], sc[1][nt * 4 + 3]));
            gp[nt] = a;
        }
        #pragma unroll
        for (int nt = 0; nt < 4; ++nt) {
            gp[nt] = add2(gp[nt], __shfl_xor_sync(0xffffffffu, gp[nt], 4));
            gp[nt] = add2(gp[nt], __shfl_xor_sync(0xffffffffu, gp[nt], 8));
            gp[nt] = add2(gp[nt], __shfl_xor_sync(0xffffffffu, gp[nt], 16));
        }

        // ---- align g[s] with V rows: lane needs g[g+8j]; src lane = lane>>3 ----
        const int src  = lane >> 3;
        const int bsel = (lane >> 2) & 1;
        float gv[4];
        #pragma unroll
        for (int j = 0; j < 4; ++j) {
            ull gs = __shfl_sync(0xffffffffu, gp[j], src);
            float lo, hi; unpack2(gs, lo, hi);
            gv[j] = bsel ? hi : lo;
        }

        // ---- c[n] = sum_s g[s] V[s][n]; reduce over g-lanes ----
        ull g00 = pack2(gv[0], gv[0]), g11 = pack2(gv[1], gv[1]);
        ull g22 = pack2(gv[2], gv[2]), g33 = pack2(gv[3], gv[3]);
        ull cp01 = 0ull, cp23 = 0ull;
        fma2(cp01, g00, pack2(acc[4][0], acc[4][1]));
        fma2(cp01, g11, pack2(acc[4][2], acc[4][3]));
        fma2(cp01, g22, pack2(acc[5][0], acc[5][1]));
        fma2(cp01, g33, pack2(acc[5][2], acc[5][3]));
        fma2(cp23, g00, pack2(acc[4][4], acc[4][5]));
        fma2(cp23, g11, pack2(acc[4][6], acc[4][7]));
        fma2(cp23, g22, pack2(acc[5][4], acc[5][5]));
        fma2(cp23, g33, pack2(acc[5][6], acc[5][7]));
        cp01 = add2(cp01, __shfl_xor_sync(0xffffffffu, cp01, 4));
        cp01 = add2(cp01, __shfl_xor_sync(0xffffffffu, cp01, 8));
        cp01 = add2(cp01, __shfl_xor_sync(0xffffffffu, cp01, 16));
        cp23 = add2(cp23, __shfl_xor_sync(0xffffffffu, cp23, 4));
        cp23 = add2(cp23, __shfl_xor_sync(0xffffffffu, cp23, 8));
        cp23 = add2(cp23, __shfl_xor_sync(0xffffffffu, cp23, 16));
        float c0, c1, c2, c3;
        unpack2(cp01, c0, c1); unpack2(cp23, c2, c3);

        // ---- tanh^2, rowsum (quad), Laplacian write (lanes 0-3) ----
        float t0 = fast_tanh(c0), t1 = fast_tanh(c1);
        float t2 = fast_tanh(c2), t3 = fast_tanh(c3);
        float r20 = t0 * t0, r21 = t1 * t1, r22 = t2 * t2, r23 = t3 * t3;
        float rs = r20 + r21 + r22 + r23;
        rs += __shfl_xor_sync(0xffffffffu, rs, 1);
        rs += __shfl_xor_sync(0xffffffffu, rs, 2);

        if (lane < 4) {
            int i  = b & 15;
            int n0 = 2 * lane;
            int n2 = 8 + 2 * lane;
            float* op = out + (size_t)b * 16;
            *(float2*)(op + n0) = make_float2(
                (n0     == i) ? rs : -r20,
                (n0 + 1 == i) ? rs : -r21);
            *(float2*)(op + n2) = make_float2(
                (n2     == i) ? rs : -r22,
                (n2 + 1 == i) ? rs : -r23);
        }
        __syncwarp();
    }
}

extern "C" void kernel_launch(void* const* d_in, const int* in_sizes, int n_in,
                              void* d_out, int out_size) {
    const float* x  = (const float*)d_in[0];
    const float* L  = (const float*)d_in[1];
    const float* Aq = (const float*)d_in[2];
    const float* Ak = (const float*)d_in[3];
    const float* Av = (const float*)d_in[4];
    const float* Ao = (const float*)d_in[5];
    float* out = (float*)d_out;

    cudaFuncSetAttribute(att_mask_kernel,
                         cudaFuncAttributeMaxDynamicSharedMemorySize, SMEM_BYTES);
    att_mask_kernel<<<NCTAS, THREADS, SMEM_BYTES>>>(x, L, Aq, Ak, Av, Ao, out);
}

// round 10
// speedup vs baseline: 2.6718x; 1.1216x over previous
#include <cuda_runtime.h>
#include <cuda_bf16.h>
#include <cstdint>

// Att_mask R10: R8 register-resident pipeline, occupancy push.
// 256-thread blocks + __launch_bounds__(256,3) -> ptxas <=85 regs ->
// 3 CTAs/SM = 24 warps (was 16). Algorithm identical to R8 (proven):
//   split-bf16 HMMA projection -> tanh in regs -> in-register score mma
//   (C-fragment layout identity) -> shuffle-tree softmax/g-trick/V contraction.

typedef unsigned long long ull;

#define THREADS 256
#define WPB     8
#define NCTAS   2048
#define ITERS   4            // 2048 * 8 warps * 4 = 65536 batches

#define SM_WHI   0           // 96 rows x 128B bf16, chunk-swizzled
#define SM_WLO   12288
#define SM_WARP0 24576
#define PW_BYTES 6144        // per-warp: xhi 3072 | xlo 3072
#define SMEM_BYTES (SM_WARP0 + WPB * PW_BYTES + 128)

#define XROW_B   48          // x bf16 tile row stride (conflict-free LDSM.trans)

// ---------------- packed f32x2 helpers ----------------
__device__ __forceinline__ ull pack2(float lo, float hi) {
    ull r; asm("mov.b64 %0, {%1, %2};" : "=l"(r) : "f"(lo), "f"(hi)); return r;
}
__device__ __forceinline__ void unpack2(ull v, float& lo, float& hi) {
    asm("mov.b64 {%0, %1}, %2;" : "=f"(lo), "=f"(hi) : "l"(v));
}
__device__ __forceinline__ void fma2(ull& d, ull a, ull b) {
    asm("fma.rn.f32x2 %0, %1, %2, %0;" : "+l"(d) : "l"(a), "l"(b));
}
__device__ __forceinline__ ull add2(ull a, ull b) {
    ull r; asm("add.rn.f32x2 %0, %1, %2;" : "=l"(r) : "l"(a), "l"(b)); return r;
}
__device__ __forceinline__ float ex2f(float x) {
    float r; asm("ex2.approx.f32 %0, %1;" : "=f"(r) : "f"(x)); return r;
}
__device__ __forceinline__ float fast_tanh(float x) {      // 1-2/(e^2x+1), ~1e-6
    float e = ex2f(2.8853900817779268f * x);
    return 1.0f - __fdividef(2.0f, e + 1.0f);
}

// ---------------- smem / mma helpers ----------------
__device__ __forceinline__ unsigned smem_u32(const void* p) {
    unsigned a;
    asm("{ .reg .u64 t; cvta.to.shared.u64 t, %1; cvt.u32.u64 %0, t; }" : "=r"(a) : "l"(p));
    return a;
}
__device__ __forceinline__ unsigned cvtpack2(float lo, float hi) {
    unsigned r; asm("cvt.rn.bf16x2.f32 %0, %1, %2;" : "=r"(r) : "f"(hi), "f"(lo)); return r;
}
__device__ __forceinline__ void split_pair(float a, float b, unsigned& hi, unsigned& lo) {
    hi = cvtpack2(a, b);
    float ha = __uint_as_float(hi << 16);
    float hb = __uint_as_float(hi & 0xffff0000u);
    lo = cvtpack2(a - ha, b - hb);
}
__device__ __forceinline__ void ldsm_x4(unsigned r[4], unsigned addr) {
    asm volatile("ldmatrix.sync.aligned.m8n8.x4.shared.b16 {%0,%1,%2,%3}, [%4];"
                 : "=r"(r[0]), "=r"(r[1]), "=r"(r[2]), "=r"(r[3]) : "r"(addr));
}
__device__ __forceinline__ void ldsm_x4_t(unsigned r[4], unsigned addr) {
    asm volatile("ldmatrix.sync.aligned.m8n8.x4.trans.shared.b16 {%0,%1,%2,%3}, [%4];"
                 : "=r"(r[0]), "=r"(r[1]), "=r"(r[2]), "=r"(r[3]) : "r"(addr));
}
__device__ __forceinline__ void mma_bf16(float* c, const unsigned* a, const unsigned* b) {
    asm volatile("mma.sync.aligned.m16n8k16.row.col.f32.bf16.bf16.f32 "
                 "{%0,%1,%2,%3}, {%4,%5,%6,%7}, {%8,%9}, {%0,%1,%2,%3};"
                 : "+f"(c[0]), "+f"(c[1]), "+f"(c[2]), "+f"(c[3])
                 : "r"(a[0]), "r"(a[1]), "r"(a[2]), "r"(a[3]), "r"(b[0]), "r"(b[1]));
}
__device__ __forceinline__ void sts_v2(unsigned addr, unsigned a, unsigned b) {
    asm volatile("st.shared.v2.b32 [%0], {%1, %2};" :: "r"(addr), "r"(a), "r"(b));
}

__global__ void __launch_bounds__(THREADS, 3) att_mask_kernel(
    const float* __restrict__ x, const float* __restrict__ L,
    const float* __restrict__ Aq, const float* __restrict__ Ak,
    const float* __restrict__ Av, const float* __restrict__ Ao,
    float* __restrict__ out)
{
    extern __shared__ char smem[];
    const int tid  = threadIdx.x;
    const int warp = tid >> 5;
    const int lane = tid & 31;
    const int g    = lane >> 2;          // fragment group (row)
    const unsigned smem_base = smem_u32(smem);

    // ---- stage W split-bf16, chunk-swizzled [96 rows][128B] (proven) ----
    for (int idx = tid; idx < 6144; idx += THREADS) {
        int row = idx >> 6, d = idx & 63;
        float val = (row < 32) ? Aq[row * 64 + d]
                  : (row < 64) ? Ak[(row - 32) * 64 + d]
                               : Av[(row - 64) * 64 + d];
        __nv_bfloat16 h = __float2bfloat16(val);
        __nv_bfloat16 l = __float2bfloat16(val - __bfloat162float(h));
        int off = row * 128 + (((d >> 3) ^ (row & 7)) << 4) + (d & 7) * 2;
        *(__nv_bfloat16*)(smem + SM_WHI + off) = h;
        *(__nv_bfloat16*)(smem + SM_WLO + off) = l;
    }
    float aoR0 = __ldg(Ao + g);
    float aoR1 = __ldg(Ao + g + 8);
    float aoR2 = __ldg(Ao + g + 16);
    float aoR3 = __ldg(Ao + g + 24);
    __syncthreads();

    const unsigned xhib = smem_base + SM_WARP0 + warp * PW_BYTES;
    const unsigned xlob = xhib + 3072;

    // ldmatrix lane addressing (proven)
    const int lm = lane >> 3;
    const int li = lane & 7;
    const unsigned a_row  = ((lm & 1) << 3) + li;
    const unsigned a_cb   = (unsigned)(lm >> 1);
    const unsigned b_roff = (((lm & 1) << 3) + li) * XROW_B + ((lm >> 1) << 4);

    const int gw = blockIdx.x * WPB + warp;

    for (int it = 0; it < ITERS; ++it) {
        const int b = gw * ITERS + it;

        // ---- load x coalesced + L ----
        const float4* xg4 = (const float4*)(x + (size_t)b * 1024);
        float4 xv[8];
        #pragma unroll
        for (int j = 0; j < 8; ++j) xv[j] = xg4[j * 32 + lane];
        float lv = (lane < 16) ? __ldg(L + (size_t)b * 256 + lane) : 0.0f;

        __syncwarp();

        // ---- convert x to bf16 hi/lo tiles [d=64][n=16], rows 48B ----
        #pragma unroll
        for (int j = 0; j < 8; ++j) {
            float4 v = xv[j];
            unsigned h01 = cvtpack2(v.x, v.y);
            unsigned h23 = cvtpack2(v.z, v.w);
            float f0 = __uint_as_float(h01 << 16);
            float f1 = __uint_as_float(h01 & 0xffff0000u);
            float f2 = __uint_as_float(h23 << 16);
            float f3 = __uint_as_float(h23 & 0xffff0000u);
            unsigned l01 = cvtpack2(v.x - f0, v.y - f1);
            unsigned l23 = cvtpack2(v.z - f2, v.w - f3);
            unsigned off = (unsigned)((8 * j + (lane >> 2)) * XROW_B + (lane & 3) * 8);
            sts_v2(xhib + off, h01, h23);
            sts_v2(xlob + off, l01, l23);
        }
        __syncwarp();

        // ---- projection: 3 terms x (6 mt x 2 nt x 4 kt) mma.sync ----
        float acc[6][8];
        #pragma unroll
        for (int mt = 0; mt < 6; ++mt)
            #pragma unroll
            for (int p = 0; p < 8; ++p) acc[mt][p] = 0.0f;

        #pragma unroll
        for (int kt = 0; kt < 4; ++kt) {
            unsigned bh[4], bl[4];
            unsigned boff = (unsigned)(kt * 16 * XROW_B) + b_roff;
            ldsm_x4_t(bh, xhib + boff);
            ldsm_x4_t(bl, xlob + boff);
            unsigned ach = (((kt * 2 + a_cb) ^ li) << 4);
            #pragma unroll
            for (int mt = 0; mt < 6; ++mt) {
                unsigned ah[4], al[4];
                unsigned arow = (unsigned)(mt * 16 + a_row) * 128 + ach;
                ldsm_x4(ah, smem_base + SM_WHI + arow);
                ldsm_x4(al, smem_base + SM_WLO + arow);
                mma_bf16(acc[mt] + 0, ah, bh + 0);
                mma_bf16(acc[mt] + 4, ah, bh + 2);
                mma_bf16(acc[mt] + 0, ah, bl + 0);
                mma_bf16(acc[mt] + 4, ah, bl + 2);
                mma_bf16(acc[mt] + 0, al, bh + 0);
                mma_bf16(acc[mt] + 4, al, bh + 2);
            }
        }

        // ---- tanh on all fragments ----
        #pragma unroll
        for (int mt = 0; mt < 6; ++mt)
            #pragma unroll
            for (int p = 0; p < 8; ++p) acc[mt][p] = fast_tanh(acc[mt][p]);

        unsigned mbal = __ballot_sync(0xffffffffu, lv >= 1.0f);
        float scl2 = rsqrtf((float)(__popc(mbal) + 1)) * 1.4426950408889634f;

        // ---- Q A-fragments up front (frees acc[0..1] for the allocator) ----
        unsigned qh0[4], ql0[4], qh1[4], ql1[4];
        split_pair(acc[0][0], acc[0][1], qh0[0], ql0[0]);
        split_pair(acc[0][2], acc[0][3], qh0[1], ql0[1]);
        split_pair(acc[0][4], acc[0][5], qh0[2], ql0[2]);
        split_pair(acc[0][6], acc[0][7], qh0[3], ql0[3]);
        split_pair(acc[1][0], acc[1][1], qh1[0], ql1[0]);
        split_pair(acc[1][2], acc[1][3], qh1[1], ql1[1]);
        split_pair(acc[1][4], acc[1][5], qh1[2], ql1[2]);
        split_pair(acc[1][6], acc[1][7], qh1[3], ql1[3]);

        // ---- K B-fragments straight from C fragments (layout identity) ----
        unsigned kbh[4][2], kbl[4][2];
        split_pair(acc[2][0], acc[2][1], kbh[0][0], kbl[0][0]);
        split_pair(acc[2][4], acc[2][5], kbh[0][1], kbl[0][1]);
        split_pair(acc[2][2], acc[2][3], kbh[1][0], kbl[1][0]);
        split_pair(acc[2][6], acc[2][7], kbh[1][1], kbl[1][1]);
        split_pair(acc[3][0], acc[3][1], kbh[2][0], kbl[2][0]);
        split_pair(acc[3][4], acc[3][5], kbh[2][1], kbl[2][1]);
        split_pair(acc[3][2], acc[3][3], kbh[3][0], kbl[3][0]);
        split_pair(acc[3][6], acc[3][7], kbh[3][1], kbl[3][1]);

        // ---- scores = Qt @ Kt^T : 2 mt' x 4 nt' x 3 terms ----
        float sc[2][16];
        #pragma unroll
        for (int m = 0; m < 2; ++m)
            #pragma unroll
            for (int p = 0; p < 16; ++p) sc[m][p] = 0.0f;
        #pragma unroll
        for (int nt = 0; nt < 4; ++nt) {
            mma_bf16(sc[0] + nt * 4, qh0, kbh[nt]);
            mma_bf16(sc[0] + nt * 4, qh0, kbl[nt]);
            mma_bf16(sc[0] + nt * 4, ql0, kbh[nt]);
            mma_bf16(sc[1] + nt * 4, qh1, kbh[nt]);
            mma_bf16(sc[1] + nt * 4, qh1, kbl[nt]);
            mma_bf16(sc[1] + nt * 4, ql1, kbh[nt]);
        }

        // ---- e = exp2(score * scl2) in place ----
        #pragma unroll
        for (int m = 0; m < 2; ++m)
            #pragma unroll
            for (int p = 0; p < 16; ++p) sc[m][p] = ex2f(sc[m][p] * scl2);

        // ---- esum per row; reduce over quad ----
        float rA0 = 0.0f, rA1 = 0.0f, rB0 = 0.0f, rB1 = 0.0f;
        #pragma unroll
        for (int nt = 0; nt < 4; ++nt) {
            rA0 += sc[0][nt * 4 + 0] + sc[0][nt * 4 + 1];
            rA1 += sc[0][nt * 4 + 2] + sc[0][nt * 4 + 3];
            rB0 += sc[1][nt * 4 + 0] + sc[1][nt * 4 + 1];
            rB1 += sc[1][nt * 4 + 2] + sc[1][nt * 4 + 3];
        }
        ull u0 = pack2(rA0, rA1), u1 = pack2(rB0, rB1);
        u0 = add2(u0, __shfl_xor_sync(0xffffffffu, u0, 1));
        u0 = add2(u0, __shfl_xor_sync(0xffffffffu, u0, 2));
        u1 = add2(u1, __shfl_xor_sync(0xffffffffu, u1, 1));
        u1 = add2(u1, __shfl_xor_sync(0xffffffffu, u1, 2));
        float es0, es1, es2, es3;
        unpack2(u0, es0, es1); unpack2(u1, es2, es3);
        float w0 = aoR0 * __fdividef(1.0f, es0);
        float w1 = aoR1 * __fdividef(1.0f, es1);
        float w2 = aoR2 * __fdividef(1.0f, es2);
        float w3 = aoR3 * __fdividef(1.0f, es3);

        // ---- g[s] = sum_r w[r] e[r][s]; reduce over g-lanes ----
        ull w00 = pack2(w0, w0), w11 = pack2(w1, w1);
        ull w22 = pack2(w2, w2), w33 = pack2(w3, w3);
        ull gp[4];
        #pragma unroll
        for (int nt = 0; nt < 4; ++nt) {
            ull a = 0ull;
            fma2(a, w00, pack2(sc[0][nt * 4 + 0], sc[0][nt * 4 + 1]));
            fma2(a, w11, pack2(sc[0][nt * 4 + 2], sc[0][nt * 4 + 3]));
            fma2(a, w22, pack2(sc[1][nt * 4 + 0], sc[1][nt * 4 + 1]));
            fma2(a, w33, pack2(sc[1][nt * 4 + 2], sc[1][nt * 4 + 3]));
            gp[nt] = a;
        }
        #pragma unroll
        for (int nt = 0; nt < 4; ++nt) {
            gp[nt] = add2(gp[nt], __shfl_xor_sync(0xffffffffu, gp[nt], 4));
            gp[nt] = add2(gp[nt], __shfl_xor_sync(0xffffffffu, gp[nt], 8));
            gp[nt] = add2(gp[nt], __shfl_xor_sync(0xffffffffu, gp[nt], 16));
        }

        // ---- align g[s] with V rows ----
        const int src  = lane >> 3;
        const int bsel = (lane >> 2) & 1;
        float gv[4];
        #pragma unroll
        for (int j = 0; j < 4; ++j) {
            ull gs = __shfl_sync(0xffffffffu, gp[j], src);
            float lo, hi; unpack2(gs, lo, hi);
            gv[j] = bsel ? hi : lo;
        }

        // ---- c[n] = sum_s g[s] V[s][n]; reduce over g-lanes ----
        ull g00 = pack2(gv[0], gv[0]), g11 = pack2(gv[1], gv[1]);
        ull g22 = pack2(gv[2], gv[2]), g33 = pack2(gv[3], gv[3]);
        ull cp01 = 0ull, cp23 = 0ull;
        fma2(cp01, g00, pack2(acc[4][0], acc[4][1]));
        fma2(cp01, g11, pack2(acc[4][2], acc[4][3]));
        fma2(cp01, g22, pack2(acc[5][0], acc[5][1]));
        fma2(cp01, g33, pack2(acc[5][2], acc[5][3]));
        fma2(cp23, g00, pack2(acc[4][4], acc[4][5]));
        fma2(cp23, g11, pack2(acc[4][6], acc[4][7]));
        fma2(cp23, g22, pack2(acc[5][4], acc[5][5]));
        fma2(cp23, g33, pack2(acc[5][6], acc[5][7]));
        cp01 = add2(cp01, __shfl_xor_sync(0xffffffffu, cp01, 4));
        cp01 = add2(cp01, __shfl_xor_sync(0xffffffffu, cp01, 8));
        cp01 = add2(cp01, __shfl_xor_sync(0xffffffffu, cp01, 16));
        cp23 = add2(cp23, __shfl_xor_sync(0xffffffffu, cp23, 4));
        cp23 = add2(cp23, __shfl_xor_sync(0xffffffffu, cp23, 8));
        cp23 = add2(cp23, __shfl_xor_sync(0xffffffffu, cp23, 16));
        float c0, c1, c2, c3;
        unpack2(cp01, c0, c1); unpack2(cp23, c2, c3);

        // ---- tanh^2, rowsum (quad), Laplacian write (lanes 0-3) ----
        float t0 = fast_tanh(c0), t1 = fast_tanh(c1);
        float t2 = fast_tanh(c2), t3 = fast_tanh(c3);
        float r20 = t0 * t0, r21 = t1 * t1, r22 = t2 * t2, r23 = t3 * t3;
        float rs = r20 + r21 + r22 + r23;
        rs += __shfl_xor_sync(0xffffffffu, rs, 1);
        rs += __shfl_xor_sync(0xffffffffu, rs, 2);

        if (lane < 4) {
            int i  = b & 15;
            int n0 = 2 * lane;
            int n2 = 8 + 2 * lane;
            float* op = out + (size_t)b * 16;
            *(float2*)(op + n0) = make_float2(
                (n0     == i) ? rs : -r20,
                (n0 + 1 == i) ? rs : -r21);
            *(float2*)(op + n2) = make_float2(
                (n2     == i) ? rs : -r22,
                (n2 + 1 == i) ? rs : -r23);
        }
        __syncwarp();
    }
}

extern "C" void kernel_launch(void* const* d_in, const int* in_sizes, int n_in,
                              void* d_out, int out_size) {
    const float* x  = (const float*)d_in[0];
    const float* L  = (const float*)d_in[1];
    const float* Aq = (const float*)d_in[2];
    const float* Ak = (const float*)d_in[3];
    const float* Av = (const float*)d_in[4];
    const float* Ao = (const float*)d_in[5];
    float* out = (float*)d_out;

    cudaFuncSetAttribute(att_mask_kernel,
                         cudaFuncAttributeMaxDynamicSharedMemorySize, SMEM_BYTES);
    att_mask_kernel<<<NCTAS, THREADS, SMEM_BYTES>>>(x, L, Aq, Ak, Av, Ao, out);
}